// round 17
// baseline (speedup 1.0000x reference)
#include <cuda_runtime.h>
#include <cstdint>

#define BATCH   16384
#define NF      27            // 1 dense + 26 sparse rows
#define OUTW    479           // 128 + 351
#define WPC     8             // warps (= samples) per CTA
#define THREADS 256
#define WBUF    8192          // bytes per warp: H[32x64bf16]=4K + L=4K (epilogue overlays)
#define SMEM_BYTES (WPC * WBUF)   // 65536 -> 3 CTAs/SM

// packed (i<<8 | j) for triu_indices(27, k=1), row-major order
__constant__ uint16_t c_ij[351] = {
#define R(i) \
    ((i)<<8)| (i)+1,((i)<<8)| (i)+2,((i)<<8)| (i)+3,((i)<<8)| (i)+4,((i)<<8)| (i)+5, \
    ((i)<<8)| (i)+6,((i)<<8)| (i)+7,((i)<<8)| (i)+8,((i)<<8)| (i)+9,((i)<<8)| (i)+10, \
    ((i)<<8)| (i)+11,((i)<<8)| (i)+12,((i)<<8)| (i)+13,((i)<<8)| (i)+14,((i)<<8)| (i)+15, \
    ((i)<<8)| (i)+16,((i)<<8)| (i)+17,((i)<<8)| (i)+18,((i)<<8)| (i)+19,((i)<<8)| (i)+20, \
    ((i)<<8)| (i)+21,((i)<<8)| (i)+22,((i)<<8)| (i)+23,((i)<<8)| (i)+24,((i)<<8)| (i)+25, \
    ((i)<<8)| (i)+26
    R(0),
    (1<<8)|2,(1<<8)|3,(1<<8)|4,(1<<8)|5,(1<<8)|6,(1<<8)|7,(1<<8)|8,(1<<8)|9,(1<<8)|10,
    (1<<8)|11,(1<<8)|12,(1<<8)|13,(1<<8)|14,(1<<8)|15,(1<<8)|16,(1<<8)|17,(1<<8)|18,
    (1<<8)|19,(1<<8)|20,(1<<8)|21,(1<<8)|22,(1<<8)|23,(1<<8)|24,(1<<8)|25,(1<<8)|26,
    (2<<8)|3,(2<<8)|4,(2<<8)|5,(2<<8)|6,(2<<8)|7,(2<<8)|8,(2<<8)|9,(2<<8)|10,(2<<8)|11,
    (2<<8)|12,(2<<8)|13,(2<<8)|14,(2<<8)|15,(2<<8)|16,(2<<8)|17,(2<<8)|18,(2<<8)|19,
    (2<<8)|20,(2<<8)|21,(2<<8)|22,(2<<8)|23,(2<<8)|24,(2<<8)|25,(2<<8)|26,
    (3<<8)|4,(3<<8)|5,(3<<8)|6,(3<<8)|7,(3<<8)|8,(3<<8)|9,(3<<8)|10,(3<<8)|11,(3<<8)|12,
    (3<<8)|13,(3<<8)|14,(3<<8)|15,(3<<8)|16,(3<<8)|17,(3<<8)|18,(3<<8)|19,(3<<8)|20,
    (3<<8)|21,(3<<8)|22,(3<<8)|23,(3<<8)|24,(3<<8)|25,(3<<8)|26,
    (4<<8)|5,(4<<8)|6,(4<<8)|7,(4<<8)|8,(4<<8)|9,(4<<8)|10,(4<<8)|11,(4<<8)|12,(4<<8)|13,
    (4<<8)|14,(4<<8)|15,(4<<8)|16,(4<<8)|17,(4<<8)|18,(4<<8)|19,(4<<8)|20,(4<<8)|21,
    (4<<8)|22,(4<<8)|23,(4<<8)|24,(4<<8)|25,(4<<8)|26,
    (5<<8)|6,(5<<8)|7,(5<<8)|8,(5<<8)|9,(5<<8)|10,(5<<8)|11,(5<<8)|12,(5<<8)|13,(5<<8)|14,
    (5<<8)|15,(5<<8)|16,(5<<8)|17,(5<<8)|18,(5<<8)|19,(5<<8)|20,(5<<8)|21,(5<<8)|22,
    (5<<8)|23,(5<<8)|24,(5<<8)|25,(5<<8)|26,
    (6<<8)|7,(6<<8)|8,(6<<8)|9,(6<<8)|10,(6<<8)|11,(6<<8)|12,(6<<8)|13,(6<<8)|14,(6<<8)|15,
    (6<<8)|16,(6<<8)|17,(6<<8)|18,(6<<8)|19,(6<<8)|20,(6<<8)|21,(6<<8)|22,(6<<8)|23,
    (6<<8)|24,(6<<8)|25,(6<<8)|26,
    (7<<8)|8,(7<<8)|9,(7<<8)|10,(7<<8)|11,(7<<8)|12,(7<<8)|13,(7<<8)|14,(7<<8)|15,(7<<8)|16,
    (7<<8)|17,(7<<8)|18,(7<<8)|19,(7<<8)|20,(7<<8)|21,(7<<8)|22,(7<<8)|23,(7<<8)|24,
    (7<<8)|25,(7<<8)|26,
    (8<<8)|9,(8<<8)|10,(8<<8)|11,(8<<8)|12,(8<<8)|13,(8<<8)|14,(8<<8)|15,(8<<8)|16,(8<<8)|17,
    (8<<8)|18,(8<<8)|19,(8<<8)|20,(8<<8)|21,(8<<8)|22,(8<<8)|23,(8<<8)|24,(8<<8)|25,(8<<8)|26,
    (9<<8)|10,(9<<8)|11,(9<<8)|12,(9<<8)|13,(9<<8)|14,(9<<8)|15,(9<<8)|16,(9<<8)|17,(9<<8)|18,
    (9<<8)|19,(9<<8)|20,(9<<8)|21,(9<<8)|22,(9<<8)|23,(9<<8)|24,(9<<8)|25,(9<<8)|26,
    (10<<8)|11,(10<<8)|12,(10<<8)|13,(10<<8)|14,(10<<8)|15,(10<<8)|16,(10<<8)|17,(10<<8)|18,
    (10<<8)|19,(10<<8)|20,(10<<8)|21,(10<<8)|22,(10<<8)|23,(10<<8)|24,(10<<8)|25,(10<<8)|26,
    (11<<8)|12,(11<<8)|13,(11<<8)|14,(11<<8)|15,(11<<8)|16,(11<<8)|17,(11<<8)|18,(11<<8)|19,
    (11<<8)|20,(11<<8)|21,(11<<8)|22,(11<<8)|23,(11<<8)|24,(11<<8)|25,(11<<8)|26,
    (12<<8)|13,(12<<8)|14,(12<<8)|15,(12<<8)|16,(12<<8)|17,(12<<8)|18,(12<<8)|19,(12<<8)|20,
    (12<<8)|21,(12<<8)|22,(12<<8)|23,(12<<8)|24,(12<<8)|25,(12<<8)|26,
    (13<<8)|14,(13<<8)|15,(13<<8)|16,(13<<8)|17,(13<<8)|18,(13<<8)|19,(13<<8)|20,(13<<8)|21,
    (13<<8)|22,(13<<8)|23,(13<<8)|24,(13<<8)|25,(13<<8)|26,
    (14<<8)|15,(14<<8)|16,(14<<8)|17,(14<<8)|18,(14<<8)|19,(14<<8)|20,(14<<8)|21,(14<<8)|22,
    (14<<8)|23,(14<<8)|24,(14<<8)|25,(14<<8)|26,
    (15<<8)|16,(15<<8)|17,(15<<8)|18,(15<<8)|19,(15<<8)|20,(15<<8)|21,(15<<8)|22,(15<<8)|23,
    (15<<8)|24,(15<<8)|25,(15<<8)|26,
    (16<<8)|17,(16<<8)|18,(16<<8)|19,(16<<8)|20,(16<<8)|21,(16<<8)|22,(16<<8)|23,(16<<8)|24,
    (16<<8)|25,(16<<8)|26,
    (17<<8)|18,(17<<8)|19,(17<<8)|20,(17<<8)|21,(17<<8)|22,(17<<8)|23,(17<<8)|24,(17<<8)|25,
    (17<<8)|26,
    (18<<8)|19,(18<<8)|20,(18<<8)|21,(18<<8)|22,(18<<8)|23,(18<<8)|24,(18<<8)|25,(18<<8)|26,
    (19<<8)|20,(19<<8)|21,(19<<8)|22,(19<<8)|23,(19<<8)|24,(19<<8)|25,(19<<8)|26,
    (20<<8)|21,(20<<8)|22,(20<<8)|23,(20<<8)|24,(20<<8)|25,(20<<8)|26,
    (21<<8)|22,(21<<8)|23,(21<<8)|24,(21<<8)|25,(21<<8)|26,
    (22<<8)|23,(22<<8)|24,(22<<8)|25,(22<<8)|26,
    (23<<8)|24,(23<<8)|25,(23<<8)|26,
    (24<<8)|25,(24<<8)|26,
    (25<<8)|26
#undef R
};

__device__ __forceinline__ uint32_t smem_u32(const void* p) {
    uint32_t a;
    asm("{ .reg .u64 t; cvta.to.shared.u64 t, %1; cvt.u32.u64 %0, t; }" : "=r"(a) : "l"(p));
    return a;
}
__device__ __forceinline__ void ldm4(uint32_t r[4], uint32_t addr) {
    asm volatile("ldmatrix.sync.aligned.m8n8.x4.shared.b16 {%0,%1,%2,%3}, [%4];"
                 : "=r"(r[0]), "=r"(r[1]), "=r"(r[2]), "=r"(r[3]) : "r"(addr));
}
__device__ __forceinline__ void mma16816(float d[4], const uint32_t a[4], const uint32_t b[2]) {
    asm volatile(
        "mma.sync.aligned.m16n8k16.row.col.f32.bf16.bf16.f32 "
        "{%0,%1,%2,%3}, {%4,%5,%6,%7}, {%8,%9}, {%0,%1,%2,%3};"
        : "+f"(d[0]), "+f"(d[1]), "+f"(d[2]), "+f"(d[3])
        : "r"(a[0]), "r"(a[1]), "r"(a[2]), "r"(a[3]), "r"(b[0]), "r"(b[1]));
}
__device__ __forceinline__ void sts2(uint32_t addr, float x, float y) {
    asm volatile("st.shared.v2.b32 [%0], {%1,%2};"
                 :: "r"(addr), "r"(__float_as_uint(x)), "r"(__float_as_uint(y)));
}
__device__ __forceinline__ float lds1(uint32_t addr) {
    float v;
    asm volatile("ld.shared.f32 %0, [%1];" : "=f"(v) : "r"(addr));
    return v;
}

// Per-warp buffer (one K-half at a time):
//   H rows 0..31 (row = feature; 64 bf16 = 128 B/row) at [0, 4096)
//   L rows 0..31 at [4096, 8192)
// Swizzle: 16B chunk q of row r stored at chunk (q ^ (r & 7)) -> conflict-free ldmatrix.
// Rows 27-31 hold stale data; they only pollute G rows/cols >= 27, never read.
// Epilogue overlay: G upper-left, stride 34 floats, at [0, 4352).

__device__ __forceinline__ float4 ldrow(const float* __restrict__ dense,
                                        const float* __restrict__ sparse,
                                        int b, int f, int gchunk) {
    if (f == 0)
        return reinterpret_cast<const float4*>(dense)[b * 32 + gchunk];
    if (f < NF)
        return reinterpret_cast<const float4*>(sparse)[(b * 26 + (f - 1)) * 32 + gchunk];
    return make_float4(0.f, 0.f, 0.f, 0.f);
}

// bf16 hi/lo split + swizzled store into H/L
__device__ __forceinline__ void cvstore(uint32_t buf, int f, int cl, float4 v) {
    uint32_t h01, h23, l01, l23;
    asm("cvt.rn.bf16x2.f32 %0, %1, %2;" : "=r"(h01) : "f"(v.y), "f"(v.x));
    asm("cvt.rn.bf16x2.f32 %0, %1, %2;" : "=r"(h23) : "f"(v.w), "f"(v.z));
    float s0 = v.x - __uint_as_float(h01 << 16);
    float s1 = v.y - __uint_as_float(h01 & 0xFFFF0000u);
    float s2 = v.z - __uint_as_float(h23 << 16);
    float s3 = v.w - __uint_as_float(h23 & 0xFFFF0000u);
    asm("cvt.rn.bf16x2.f32 %0, %1, %2;" : "=r"(l01) : "f"(s1), "f"(s0));
    asm("cvt.rn.bf16x2.f32 %0, %1, %2;" : "=r"(l23) : "f"(s3), "f"(s2));
    const uint32_t off = buf + f * 128 + ((((cl >> 1) ^ (f & 7))) << 4) + ((cl & 1) << 3);
    asm volatile("st.shared.v2.b32 [%0], {%1,%2};" :: "r"(off), "r"(h01), "r"(h23));
    asm volatile("st.shared.v2.b32 [%0], {%1,%2};" :: "r"(off + 4096), "r"(l01), "r"(l23));
}

__global__ __launch_bounds__(THREADS, 3)
void dlrm_mma_kernel(const float* __restrict__ dense,
                     const float* __restrict__ sparse,
                     float* __restrict__ out) {
    extern __shared__ __align__(128) char smem[];
    const int tid  = threadIdx.x;
    const int w    = tid >> 5;
    const int lane = tid & 31;
    const int b    = blockIdx.x * WPC + w;
    const uint32_t buf = smem_u32(smem) + w * WBUF;

    const int cl  = lane & 15, r2 = lane >> 4;              // load mapping
    const int rowA = (lane & 7) + ((lane >> 3) & 1) * 8;    // ldmatrix A row (+ mt*16)
    const int qsA  = (lane >> 4) & 1;
    const int rowB = (lane & 7) + ((lane >> 4) & 1) * 8;    // ldmatrix B row (+ nt*16)
    const int qsB  = (lane >> 3) & 1;

    // ---- half-0 load: batch ALL 14 LDG.128 first (max MLP), then convert ----
    float4 v0[14];
#pragma unroll
    for (int it = 0; it < 14; it++)
        v0[it] = ldrow(dense, sparse, b, 2 * it + r2, cl);
    if (r2 == 0) {                       // dense passthrough, half-0 chunks
        float* o = out + (size_t)b * OUTW + (cl << 2);
        o[0] = v0[0].x; o[1] = v0[0].y; o[2] = v0[0].z; o[3] = v0[0].w;
    }
#pragma unroll
    for (int it = 0; it < 14; it++) {
        const int f = 2 * it + r2;
        if (f < NF) cvstore(buf, f, cl, v0[it]);
    }
    __syncwarp();

    // ---- prefetch half-1 part A (7 LDGs) before compute; streams during MMAs ----
    float4 v1[7];
#pragma unroll
    for (int it = 0; it < 7; it++)
        v1[it] = ldrow(dense, sparse, b, 2 * it + r2, 16 + cl);

    // G upper tiles: (mt,nt) in {(0,0),(0,1),(0,2),(0,3),(1,2),(1,3)}; 16x8 each
    float acc[6][4];
#pragma unroll
    for (int t = 0; t < 6; t++)
#pragma unroll
        for (int i = 0; i < 4; i++) acc[t][i] = 0.f;

    // ---- compute + half-1 load/convert ----
#pragma unroll
    for (int half = 0; half < 2; half++) {
        // 4 K-steps of m16n8k16; G = H·H^T + H·L^T + L·H^T on upper tiles
#pragma unroll
        for (int k = 0; k < 4; k++) {
            const int qA = (k * 2 + qsA) ^ (rowA & 7);
            const int qB = (k * 2 + qsB) ^ (rowB & 7);
            const uint32_t pA = buf + rowA * 128 + (qA << 4);
            const uint32_t pB = buf + rowB * 128 + (qB << 4);
            uint32_t aH0[4], aH1[4], aL0[4], aL1[4];
            uint32_t bH0[4], bH1[4], bL0[4], bL1[4];
            ldm4(aH0, pA);          ldm4(aH1, pA + 2048);
            ldm4(aL0, pA + 4096);   ldm4(aL1, pA + 6144);
            ldm4(bH0, pB);          ldm4(bH1, pB + 2048);
            ldm4(bL0, pB + 4096);   ldm4(bL1, pB + 6144);
            mma16816(acc[0], aH0, bH0);      mma16816(acc[0], aH0, bL0);      mma16816(acc[0], aL0, bH0);
            mma16816(acc[1], aH0, bH0 + 2);  mma16816(acc[1], aH0, bL0 + 2);  mma16816(acc[1], aL0, bH0 + 2);
            mma16816(acc[2], aH0, bH1);      mma16816(acc[2], aH0, bL1);      mma16816(acc[2], aL0, bH1);
            mma16816(acc[3], aH0, bH1 + 2);  mma16816(acc[3], aH0, bL1 + 2);  mma16816(acc[3], aL0, bH1 + 2);
            mma16816(acc[4], aH1, bH1);      mma16816(acc[4], aH1, bL1);      mma16816(acc[4], aL1, bH1);
            mma16816(acc[5], aH1, bH1 + 2);  mma16816(acc[5], aH1, bL1 + 2);  mma16816(acc[5], aL1, bH1 + 2);
        }
        __syncwarp();

        if (half == 0) {
            // FIRST issue part-B LDGs (latency overlapped with partA convert below)
            float4 vb[7];
#pragma unroll
            for (int it = 7; it < 14; it++)
                vb[it - 7] = ldrow(dense, sparse, b, 2 * it + r2, 16 + cl);
            // dense passthrough, half-1 chunks
            if (r2 == 0) {
                float* o = out + (size_t)b * OUTW + ((16 + cl) << 2);
                o[0] = v1[0].x; o[1] = v1[0].y; o[2] = v1[0].z; o[3] = v1[0].w;
            }
            // convert prefetched part A while part B streams from DRAM
#pragma unroll
            for (int it = 0; it < 7; it++) {
                const int f = 2 * it + r2;
                if (f < NF) cvstore(buf, f, cl, v1[it]);
            }
#pragma unroll
            for (int it = 7; it < 14; it++) {
                const int f = 2 * it + r2;
                if (f < NF) cvstore(buf, f, cl, vb[it - 7]);
            }
            __syncwarp();
        }
    }

    // ---- epilogue: stage 6 G tiles into dead buffer (stride 34), gather triu ----
    {
        const int rr = lane >> 2, cc = (lane & 3) * 2;
        const int pmt[6] = {0, 0, 0, 0, 1, 1};
        const int pnt[6] = {0, 1, 2, 3, 2, 3};
#pragma unroll
        for (int t = 0; t < 6; t++) {
            const uint32_t ad = buf + (((pmt[t] * 16 + rr) * 34 + pnt[t] * 8 + cc) << 2);
            sts2(ad,           acc[t][0], acc[t][1]);
            sts2(ad + 8 * 136, acc[t][2], acc[t][3]);   // +8 rows
        }
    }
    __syncwarp();

    float* orow = out + (size_t)b * OUTW + 128;
#pragma unroll
    for (int t = 0; t < 11; t++) {
        const int p = lane + t * 32;
        if (p < 351) {
            const int ij = c_ij[p];                   // packed (i<<8 | j), const cache
            const int i = ij >> 8, j = ij & 255;
            orow[p] = lds1(buf + ((i * 34 + j) << 2));
        }
    }
}

extern "C" void kernel_launch(void* const* d_in, const int* in_sizes, int n_in,
                              void* d_out, int out_size) {
    const float* dense  = (const float*)d_in[0];   // [16384, 128] fp32
    const float* sparse = (const float*)d_in[1];   // [16384, 26, 128] fp32
    float* out = (float*)d_out;                    // [16384, 479] fp32

    cudaFuncSetAttribute(dlrm_mma_kernel,
                         cudaFuncAttributeMaxDynamicSharedMemorySize, SMEM_BYTES);
    dlrm_mma_kernel<<<BATCH / WPC, THREADS, SMEM_BYTES>>>(dense, sparse, out);
}